// round 14
// baseline (speedup 1.0000x reference)
#include <cuda_runtime.h>
#include <cuda_bf16.h>
#include <cstdint>
#include <cstddef>

#define NE 160000
#define NN 10000
typedef unsigned short u16;
typedef unsigned int u32;

// ---------------- scratch (device globals) ----------------
__device__ u16 g_XFh[(size_t)NN * 512], g_XFl[(size_t)NN * 512];
__device__ u16 g_EAh[(size_t)NE * 256], g_EAl[(size_t)NE * 256];
__device__ u16 g_EHh[(size_t)NE * 256], g_EHl[(size_t)NE * 256];
__device__ u16 g_Shh[NN * 256], g_Sll[NN * 256];
__device__ u16 g_XHh[NN * 256], g_XHl[NN * 256];
__device__ float g_U[NN * 256], g_V[NN * 256], g_P[NN * 256];
__device__ float g_S[NN * 256];
__device__ float g_CNT[NN];
__device__ float g_BC[768];            // bc_a | bc_b | bc_p
__device__ int   g_SRC[NE], g_DST[NE];
__device__ int   g_IS64;
__device__ u16 g_WTH[256 * 4416], g_WTL[256 * 4416];

// ---------------- helpers ----------------
__device__ __forceinline__ u32 smem_u32(const void* p) {
    u32 a;
    asm("{ .reg .u64 t; cvta.to.shared.u64 t, %1; cvt.u32.u64 %0, t; }" : "=r"(a) : "l"(p));
    return a;
}
__device__ __forceinline__ void cp16(u32 dst, const void* src) {
    asm volatile("cp.async.ca.shared.global [%0], [%1], 16;" :: "r"(dst), "l"(src) : "memory");
}
__device__ __forceinline__ void ldsm4(u32* r, u32 addr) {
    asm volatile("ldmatrix.sync.aligned.m8n8.x4.shared.b16 {%0,%1,%2,%3}, [%4];"
                 : "=r"(r[0]), "=r"(r[1]), "=r"(r[2]), "=r"(r[3]) : "r"(addr));
}
__device__ __forceinline__ void mma_bf16(float* d, const u32* a, u32 b0, u32 b1) {
    asm volatile(
        "mma.sync.aligned.m16n8k16.row.col.f32.bf16.bf16.f32 "
        "{%0,%1,%2,%3}, {%4,%5,%6,%7}, {%8,%9}, {%0,%1,%2,%3};"
        : "+f"(d[0]), "+f"(d[1]), "+f"(d[2]), "+f"(d[3])
        : "r"(a[0]), "r"(a[1]), "r"(a[2]), "r"(a[3]), "r"(b0), "r"(b1));
}
__device__ __forceinline__ void sts128(u32 addr, u32 a, u32 b, u32 c, u32 d) {
    asm volatile("st.shared.v4.b32 [%0], {%1,%2,%3,%4};" :: "r"(addr), "r"(a), "r"(b), "r"(c), "r"(d) : "memory");
}
__device__ __forceinline__ void split2(float o0, float o1, u32& hp, u32& lp) {
    u32 b0 = __float_as_uint(o0), b1 = __float_as_uint(o1);
    hp = (b1 & 0xFFFF0000u) | (b0 >> 16);
    float l0 = o0 - __uint_as_float(b0 & 0xFFFF0000u);
    float l1 = o1 - __uint_as_float(b1 & 0xFFFF0000u);
    asm("cvt.rn.bf16x2.f32 %0, %1, %2;" : "=r"(lp) : "f"(l1), "f"(l0));
}
__device__ __forceinline__ void wt_store(size_t o, float v) {
    u32 b = __float_as_uint(v);
    g_WTH[o] = (u16)(b >> 16);
    __nv_bfloat16 lo = __float2bfloat16_rn(v - __uint_as_float(b & 0xFFFF0000u));
    g_WTL[o] = *(u16*)&lo;
}

#define RSB   80
#define STAGE_F 61440                   // full-N stage: A 20480 | B 40960
#define STAGE_H 40960                   // half-N stage: A 20480 | B 20480
#define EXTRA 11264
#define SMEM_SZ   (2 * STAGE_F + EXTRA)
#define SMEM_HALF (2 * STAGE_H + EXTRA)

// ---------------- one consolidated setup kernel ----------------
struct WtEnt { const float* w; int K, off, stride, kofs; };
struct CompJob { const float* A; const float* B; int off, stride; };
struct SetupArgs {
    WtEnt we[8];
    CompJob ce[3];
    const float *n_b2_0, *W11a, *W11b, *e_b2_1, *p_w1, *p_b1;
    const int* ei32;
};

__global__ void setup_kernel(SetupArgs sa) {
    const int y = blockIdx.y;
    if (y < 8) {
        const WtEnt en = sa.we[y];
        int idx = blockIdx.x * blockDim.x + threadIdx.x;
        if (idx >= 256 * en.K) return;
        int n = idx / en.K, k = idx - n * en.K;
        wt_store((size_t)256 * en.off + (size_t)n * en.stride + en.kofs + k,
                 en.w[(size_t)k * 256 + n]);
    } else if (y < 11) {
        if (blockIdx.x >= 256) return;
        const CompJob en = sa.ce[y - 8];
        __shared__ float arow[256];
        int k = blockIdx.x, n = threadIdx.x;
        arow[n] = en.A[(size_t)k * 256 + n];
        __syncthreads();
        float s = 0.f;
        #pragma unroll 8
        for (int m = 0; m < 256; m++) s += arow[m] * en.B[(size_t)m * 256 + n];
        wt_store((size_t)256 * en.off + (size_t)n * en.stride + k, s);
    } else {
        if (blockIdx.x == 0) {
            int n = threadIdx.x;
            float va = 0.f, vb = 0.f, vp = 0.f;
            for (int m = 0; m < 256; m++) {
                float b2 = sa.n_b2_0[m], e2 = sa.e_b2_1[m];
                va += b2 * sa.W11a[(size_t)m * 256 + n];
                vb += b2 * sa.W11b[(size_t)m * 256 + n];
                vp += e2 * sa.p_w1[(size_t)m * 256 + n];
            }
            g_BC[n] = va;
            g_BC[256 + n] = vb;
            g_BC[512 + n] = vp + sa.p_b1[n];
        } else if (blockIdx.x == 1) {
            __shared__ int any_nonzero;
            if (threadIdx.x == 0) any_nonzero = 0;
            __syncthreads();
            for (int i = threadIdx.x; i < 2048; i += blockDim.x) {
                int pos = 2 * (i * (NE / 2048)) + 1;
                if (sa.ei32[pos] != 0) any_nonzero = 1;
            }
            __syncthreads();
            if (threadIdx.x == 0) g_IS64 = any_nonzero ? 0 : 1;
        } else {
            int idx = (blockIdx.x - 2) * blockDim.x + threadIdx.x;
            int stride = (gridDim.x - 2) * blockDim.x;
            for (int j = idx; j < NN * 256; j += stride) g_S[j] = 0.f;
            for (int j = idx; j < NN; j += stride) g_CNT[j] = 0.f;
        }
    }
}

// idx convert + count + out init + x split
__global__ void prep_kernel(const int* __restrict__ ei32, const float* __restrict__ x,
                            float* __restrict__ outp, const float* __restrict__ b2) {
    int i = blockIdx.x * blockDim.x + threadIdx.x;
    int stride = gridDim.x * blockDim.x;
    const int is64 = g_IS64;
    const float bv = b2[0];
    for (int j = i; j < NE; j += stride) {
        int s, d;
        if (is64) { s = ei32[2 * j]; d = ei32[2 * (NE + j)]; }
        else      { s = ei32[j];     d = ei32[NE + j]; }
        s = min(max(s, 0), NN - 1);
        d = min(max(d, 0), NN - 1);
        g_SRC[j] = s;
        g_DST[j] = d;
        atomicAdd(&g_CNT[d], 1.f);
        outp[j] = bv;
    }
    for (int j = i; j < NN * 512; j += stride) {
        float v = x[j];
        u32 b = __float_as_uint(v);
        g_XFh[j] = (u16)(b >> 16);
        __nv_bfloat16 lo = __float2bfloat16_rn(v - __uint_as_float(b & 0xFFFF0000u));
        g_XFl[j] = *(u16*)&lo;
    }
}

__global__ void mean_kernel() {
    int n = blockIdx.x, c = threadIdx.x;
    float v = g_S[n * 256 + c] / fmaxf(g_CNT[n], 1.f);
    u32 b = __float_as_uint(v);
    g_Shh[n * 256 + c] = (u16)(b >> 16);
    __nv_bfloat16 lo = __float2bfloat16_rn(v - __uint_as_float(b & 0xFFFF0000u));
    g_Sll[n * 256 + c] = *(u16*)&lo;
}

// ---------------- unified HMMA GEMM ----------------
struct GP {
    int M, nch, Kpad;
    const u16 *A0h, *A0l; const int* I0; int w0, ld0;
    const u16 *A1h, *A1l; const int* I1; int ld1;
    const u16 *WtH, *WtL;
    const float* bias;
    const float* G1; const int* IG1;
    const float* G2; const int* IG2;
    const int* SDST;
    float* Cf; u16 *Ch, *Cl;
    const float *Uf, *Vf, *EAT, *W1c, *B1;   // COMB
    const float* PW2; float* OutP;           // PRED
    const u16* jwh[3]; const u16* jwl[3]; float* jcf[3]; const float* jb[3]; int njobs;
};

template<bool RELU, bool SPLIT, bool ADD, bool SCAT, bool COMB, bool PRED, bool NHALF>
__global__ void __launch_bounds__(256, 1) gemm3(GP p)
{
    extern __shared__ __align__(128) char smem[];
    const u32 sb = smem_u32(smem);
    const int tid = threadIdx.x;
    const int lane = tid & 31, wid = tid >> 5;
    const int warp_m = wid & 1, warp_n = wid >> 1;
    const int bm = blockIdx.x * 128;

    constexpr int STG = NHALF ? STAGE_H : STAGE_F;
    constexpr int NFR = NHALF ? 4 : 8;      // N-frags per warp (x8 cols each... 2 per nf)
    constexpr int WNT = NHALF ? 32 : 64;    // warp N tile
    const int gnb = NHALF ? (int)blockIdx.y * 128 : 0;

    const u16* WtH = p.WtH; const u16* WtL = p.WtL; float* Cf = p.Cf;
    const float* bias = p.bias;
    if (!NHALF && p.njobs) {
        int jy = blockIdx.y;
        WtH = p.jwh[jy]; WtL = p.jwl[jy]; Cf = p.jcf[jy]; bias = p.jb[jy];
    }

    const int arow = tid >> 1, ahalf = tid & 1;
    const int gmc = min(bm + arow, p.M - 1);
    const int r0i = p.I0 ? p.I0[gmc] : gmc;
    const int r1i = p.I1 ? p.I1[gmc] : gmc;
    const u16* pa0h = p.A0h ? (p.A0h + (size_t)r0i * p.ld0) : nullptr;
    const u16* pa0l = p.A0l ? (p.A0l + (size_t)r0i * p.ld0) : nullptr;
    const u16* pa1h = p.A1h ? (p.A1h + (size_t)r1i * p.ld1) : nullptr;
    const u16* pa1l = p.A1l ? (p.A1l + (size_t)r1i * p.ld1) : nullptr;
    // B pointers: full-N -> thread owns row tid; half-N -> row gnb + (tid>>1), k-half (tid&1)
    const u16* pbh;
    const u16* pbl;
    if (NHALF) {
        pbh = WtH + (size_t)(gnb + (tid >> 1)) * p.Kpad;
        pbl = WtL + (size_t)(gnb + (tid >> 1)) * p.Kpad;
    } else {
        pbh = WtH + (size_t)tid * p.Kpad;
        pbl = WtL + (size_t)tid * p.Kpad;
    }

    float acc[4][NFR][4];
    #pragma unroll
    for (int a = 0; a < 4; a++)
        #pragma unroll
        for (int b = 0; b < NFR; b++)
            #pragma unroll
            for (int c = 0; c < 4; c++) acc[a][b][c] = 0.f;

    auto prefetchB = [&](int c) {
        const int k0 = c << 5;
        if (NHALF) {
            u32 db = sb + (c & 1) * STG + 20480 + (u32)(tid >> 1) * RSB + (tid & 1) * 32;
            const int ko = k0 + (tid & 1) * 16;
            cp16(db,              pbh + ko);
            cp16(db + 16,         pbh + ko + 8);
            cp16(db + 10240,      pbl + ko);
            cp16(db + 10240 + 16, pbl + ko + 8);
        } else {
            u32 db = sb + (c & 1) * STG + 20480 + (u32)tid * RSB;
            #pragma unroll
            for (int j = 0; j < 4; j++) {
                cp16(db + j * 16,         pbh + k0 + j * 8);
                cp16(db + 20480 + j * 16, pbl + k0 + j * 8);
            }
        }
    };
    auto prefetchA = [&](int c) {
        const int k0 = c << 5;
        const u32 st = sb + (c & 1) * STG;
        const u16 *sh, *sl;
        int kk;
        if (k0 < p.w0) { sh = pa0h; sl = pa0l; kk = k0; }
        else           { sh = pa1h; sl = pa1l; kk = k0 - p.w0; }
        u32 da = st + (u32)arow * RSB + ahalf * 32;
        cp16(da,              sh + kk + ahalf * 16);
        cp16(da + 16,         sh + kk + ahalf * 16 + 8);
        cp16(da + 10240,      sl + kk + ahalf * 16);
        cp16(da + 10240 + 16, sl + kk + ahalf * 16 + 8);
    };

    // ---- COMB state (R11-proven: register prefetch at distance 1) ----
    float eav[6];
    float fu[16], fv[16];
    const float* w1ct = (const float*)(smem + 2 * STG);
    float* eas = (float*)(smem + 2 * STG + 8192);

    auto comb_load = [&](int c) {
        const int kb = (c << 5) + ahalf * 16;
        #pragma unroll
        for (int j = 0; j < 4; j++) {
            *(float4*)&fu[4 * j] = *(const float4*)&p.Uf[(size_t)r0i * 256 + kb + 4 * j];
            *(float4*)&fv[4 * j] = *(const float4*)&p.Vf[(size_t)r1i * 256 + kb + 4 * j];
        }
    };
    auto comb_convert = [&](int c) {
        const int kb = (c << 5) + ahalf * 16;
        const u32 st = sb + (c & 1) * STG;
        u32 hw[8], lw[8];
        #pragma unroll
        for (int j = 0; j < 8; j++) {
            float t[2];
            #pragma unroll
            for (int q = 0; q < 2; q++) {
                int kl = 2 * j + q;
                int k = kb + kl;
                float4 wa = *(const float4*)&w1ct[k * 8];
                float4 wb = *(const float4*)&w1ct[k * 8 + 4];
                float v = fu[kl] + fv[kl] + wb.z
                        + eav[0] * wa.x + eav[1] * wa.y + eav[2] * wa.z + eav[3] * wa.w
                        + eav[4] * wb.x + eav[5] * wb.y;
                t[q] = fmaxf(v, 0.f);
            }
            u32 b0 = __float_as_uint(t[0]), b1 = __float_as_uint(t[1]);
            hw[j] = (b1 & 0xFFFF0000u) | (b0 >> 16);
            float l0 = t[0] - __uint_as_float(b0 & 0xFFFF0000u);
            float l1 = t[1] - __uint_as_float(b1 & 0xFFFF0000u);
            asm("cvt.rn.bf16x2.f32 %0, %1, %2;" : "=r"(lw[j]) : "f"(l1), "f"(l0));
        }
        u32 da = st + (u32)arow * RSB + ahalf * 32;
        sts128(da,              hw[0], hw[1], hw[2], hw[3]);
        sts128(da + 16,         hw[4], hw[5], hw[6], hw[7]);
        sts128(da + 10240,      lw[0], lw[1], lw[2], lw[3]);
        sts128(da + 10240 + 16, lw[4], lw[5], lw[6], lw[7]);
    };

    // ---- prologue ----
    if constexpr (COMB) {
        float* w1w = (float*)(smem + 2 * STG);
        for (int i = tid; i < 2048; i += 256) {
            int k = i >> 3, jj = i & 7;
            float v = 0.f;
            if (jj < 6) v = p.W1c[jj * 256 + k];
            else if (jj == 6) v = p.B1[k];
            w1w[i] = v;
        }
        for (int i = tid; i < 768; i += 256) {
            int e = bm + i / 6, j = i % 6;
            eas[i] = (e < p.M) ? p.EAT[(size_t)e * 6 + j] : 0.f;
        }
        __syncthreads();
        #pragma unroll
        for (int j = 0; j < 6; j++) eav[j] = eas[arow * 6 + j];
        comb_load(0);
        prefetchB(0);
        asm volatile("cp.async.commit_group;" ::: "memory");
        comb_convert(0);
    } else {
        if constexpr (PRED) {
            ((float*)(smem + 2 * STG))[tid] = p.PW2[tid];
        }
        prefetchA(0); prefetchB(0);
        asm volatile("cp.async.commit_group;" ::: "memory");
    }

    // ---- mainloop ----
    for (int c = 0; c < p.nch; c++) {
        if (c + 1 < p.nch) {
            if constexpr (COMB) { comb_load(c + 1); prefetchB(c + 1); }
            else { prefetchA(c + 1); prefetchB(c + 1); }
            asm volatile("cp.async.commit_group;" ::: "memory");
            asm volatile("cp.async.wait_group 1;" ::: "memory");
        } else {
            asm volatile("cp.async.wait_group 0;" ::: "memory");
        }
        __syncthreads();

        const u32 st = sb + (c & 1) * STG;
        const u32 aH = st, aL = st + 10240, bH = st + 20480;
        const u32 bL = st + (NHALF ? 30720 : 40960);
        #pragma unroll
        for (int kk = 0; kk < 2; kk++) {
            u32 Afh[4][4], Afl[4][4];
            #pragma unroll
            for (int mf = 0; mf < 4; mf++) {
                u32 off = (u32)(warp_m * 64 + mf * 16 + (lane & 15)) * RSB
                        + kk * 32 + ((lane >> 4) << 4);
                ldsm4(Afh[mf], aH + off);
                ldsm4(Afl[mf], aL + off);
            }
            #pragma unroll
            for (int nf = 0; nf < NFR / 2; nf++) {
                u32 off = (u32)(warp_n * WNT + nf * 16 + ((lane >> 4) & 1) * 8 + (lane & 7)) * RSB
                        + kk * 32 + ((lane >> 3) & 1) * 16;
                u32 bh[4], bl[4];
                ldsm4(bh, bH + off);
                ldsm4(bl, bL + off);
                #pragma unroll
                for (int mf = 0; mf < 4; mf++) {
                    mma_bf16(acc[mf][2 * nf],     Afh[mf], bh[0], bh[1]);
                    mma_bf16(acc[mf][2 * nf + 1], Afh[mf], bh[2], bh[3]);
                }
                #pragma unroll
                for (int mf = 0; mf < 4; mf++) {
                    mma_bf16(acc[mf][2 * nf],     Afh[mf], bl[0], bl[1]);
                    mma_bf16(acc[mf][2 * nf + 1], Afh[mf], bl[2], bl[3]);
                }
                #pragma unroll
                for (int mf = 0; mf < 4; mf++) {
                    mma_bf16(acc[mf][2 * nf],     Afl[mf], bh[0], bh[1]);
                    mma_bf16(acc[mf][2 * nf + 1], Afl[mf], bh[2], bh[3]);
                }
            }
        }
        if constexpr (COMB) { if (c + 1 < p.nch) comb_convert(c + 1); }
        __syncthreads();
    }

    // ---- epilogue ----
    const int gid = lane >> 2, tig = lane & 3;
    #pragma unroll
    for (int mf = 0; mf < 4; mf++) {
        #pragma unroll
        for (int half = 0; half < 2; half++) {
            const int r = bm + warp_m * 64 + mf * 16 + half * 8 + gid;
            if constexpr (PRED) {
                const float* w2s = (const float*)(smem + 2 * STG);
                float s = 0.f;
                if (r < p.M) {
                    #pragma unroll
                    for (int nidx = 0; nidx < NFR; nidx++) {
                        const int col = warp_n * WNT + nidx * 8 + tig * 2;
                        float o0 = acc[mf][nidx][half * 2 + 0] + bias[col];
                        float o1 = acc[mf][nidx][half * 2 + 1] + bias[col + 1];
                        o0 = fmaxf(o0, 0.f); o1 = fmaxf(o1, 0.f);
                        s += o0 * w2s[col] + o1 * w2s[col + 1];
                    }
                }
                s += __shfl_xor_sync(0xffffffffu, s, 1);
                s += __shfl_xor_sync(0xffffffffu, s, 2);
                if (tig == 0 && r < p.M) atomicAdd(&p.OutP[r], s);
            } else if (r < p.M) {
                const float* ag1 = nullptr;
                const float* ag2 = nullptr;
                int sd = 0;
                if (ADD) {
                    ag1 = p.G1 + (size_t)(p.IG1 ? p.IG1[r] : r) * 256;
                    if (p.G2) ag2 = p.G2 + (size_t)(p.IG2 ? p.IG2[r] : r) * 256;
                }
                if (SCAT) sd = p.SDST[r];
                #pragma unroll
                for (int nidx = 0; nidx < NFR; nidx++) {
                    const int col = gnb + warp_n * WNT + nidx * 8 + tig * 2;
                    float o0 = acc[mf][nidx][half * 2 + 0];
                    float o1 = acc[mf][nidx][half * 2 + 1];
                    if (bias) { o0 += bias[col]; o1 += bias[col + 1]; }
                    if (ADD) {
                        o0 += ag1[col]; o1 += ag1[col + 1];
                        if (ag2) { o0 += ag2[col]; o1 += ag2[col + 1]; }
                    }
                    if (RELU) { o0 = fmaxf(o0, 0.f); o1 = fmaxf(o1, 0.f); }
                    if (SCAT) {
                        asm volatile("red.global.add.v2.f32 [%0], {%1,%2};"
                                     :: "l"(&Cf[(size_t)sd * 256 + col]), "f"(o0), "f"(o1)
                                     : "memory");
                    } else if (SPLIT) {
                        u32 hp, lp;
                        split2(o0, o1, hp, lp);
                        *(u32*)&p.Ch[(size_t)r * 256 + col] = hp;
                        *(u32*)&p.Cl[(size_t)r * 256 + col] = lp;
                    } else {
                        *(float2*)&Cf[(size_t)r * 256 + col] = make_float2(o0, o1);
                    }
                }
            }
        }
    }
}

extern "C" void kernel_launch(void* const* d_in, const int* in_sizes, int n_in,
                              void* d_out, int out_size)
{
    const float* x      = (const float*)d_in[0];
    const int*   ei32   = (const int*)d_in[1];
    const float* eattr  = (const float*)d_in[2];
    const float* e_w1_0 = (const float*)d_in[3];
    const float* e_b1_0 = (const float*)d_in[4];
    const float* e_w2_0 = (const float*)d_in[5];
    const float* e_b2_0 = (const float*)d_in[6];
    const float* n_wm_0 = (const float*)d_in[7];
    const float* n_bm_0 = (const float*)d_in[8];
    const float* n_w1_0 = (const float*)d_in[9];
    const float* n_b1_0 = (const float*)d_in[10];
    const float* n_w2_0 = (const float*)d_in[11];
    const float* n_b2_0 = (const float*)d_in[12];
    const float* e_w1_1 = (const float*)d_in[13];
    const float* e_b1_1 = (const float*)d_in[14];
    const float* e_w2_1 = (const float*)d_in[15];
    const float* e_b2_1 = (const float*)d_in[16];
    // d_in[17..22]: layer-1 node model — dead code for the output
    const float* p_w1   = (const float*)d_in[23];
    const float* p_b1   = (const float*)d_in[24];
    const float* p_w2   = (const float*)d_in[25];
    const float* p_b2   = (const float*)d_in[26];
    float* out = (float*)d_out;

#define SYM(T, v, s) T* v; cudaGetSymbolAddress((void**)&v, s)
    SYM(u16, XFh, g_XFh); SYM(u16, XFl, g_XFl);
    SYM(u16, EAh, g_EAh); SYM(u16, EAl, g_EAl);
    SYM(u16, EHh, g_EHh); SYM(u16, EHl, g_EHl);
    SYM(u16, Shh, g_Shh); SYM(u16, Sll, g_Sll);
    SYM(u16, XHh, g_XHh); SYM(u16, XHl, g_XHl);
    SYM(float, U, g_U); SYM(float, V, g_V); SYM(float, P, g_P);
    SYM(float, S, g_S); SYM(float, BC, g_BC);
    SYM(int, SRC, g_SRC); SYM(int, DST, g_DST);
    SYM(u16, WTH, g_WTH); SYM(u16, WTL, g_WTL);
#undef SYM

#define P0 gemm3<false, false, false, false, false, false, false>
#define PC gemm3<false, true,  false, false, true,  false, true >
#define P3 gemm3<true,  false, true,  true,  false, false, false>
#define P1 gemm3<true,  true,  false, false, false, false, false>
#define P4 gemm3<true,  true,  true,  false, false, false, false>
#define P6 gemm3<true,  false, false, false, false, true,  false>
    cudaFuncSetAttribute(P0, cudaFuncAttributeMaxDynamicSharedMemorySize, SMEM_SZ);
    cudaFuncSetAttribute(PC, cudaFuncAttributeMaxDynamicSharedMemorySize, SMEM_HALF);
    cudaFuncSetAttribute(P3, cudaFuncAttributeMaxDynamicSharedMemorySize, SMEM_SZ);
    cudaFuncSetAttribute(P1, cudaFuncAttributeMaxDynamicSharedMemorySize, SMEM_SZ);
    cudaFuncSetAttribute(P4, cudaFuncAttributeMaxDynamicSharedMemorySize, SMEM_SZ);
    cudaFuncSetAttribute(P6, cudaFuncAttributeMaxDynamicSharedMemorySize, SMEM_SZ);

    // weight map (k-units): W1a@0(512) W1b@512(512) e_w2_0@1024(256) Wm_a@1280(512)
    // Wm_b@1792(256) n_w1_0@2048(768) W11c@2816(256) [W21@p_w1 | p_w1]@3072(K=512)
    // Wc_a@3584(256) Wc_b@3840(256)
    SetupArgs sa{};
    sa.we[0] = { e_w1_0,             512, 0,    512, 0 };
    sa.we[1] = { e_w1_0 + 512 * 256, 512, 512,  512, 0 };
    sa.we[2] = { e_w2_0,             256, 1024, 256, 0 };
    sa.we[3] = { n_wm_0,             512, 1280, 512, 0 };
    sa.we[4] = { n_wm_0 + 512 * 256, 256, 1792, 256, 0 };
    sa.we[5] = { n_w1_0,             768, 2048, 768, 0 };
    sa.we[6] = { e_w1_1 + 512 * 256, 256, 2816, 256, 0 };
    sa.we[7] = { p_w1,               256, 3072, 512, 256 };
    sa.ce[0] = { n_w2_0, e_w1_1,             3584, 256 };
    sa.ce[1] = { n_w2_0, e_w1_1 + 256 * 256, 3840, 256 };
    sa.ce[2] = { e_w2_1, p_w1,               3072, 512 };
    sa.n_b2_0 = n_b2_0; sa.W11a = e_w1_1; sa.W11b = e_w1_1 + 256 * 256;
    sa.e_b2_1 = e_b2_1; sa.p_w1 = p_w1; sa.p_b1 = p_b1;
    sa.ei32 = ei32;
    setup_kernel<<<dim3(768, 12), 256>>>(sa);

    prep_kernel<<<2048, 256>>>(ei32, x, out, p_b2);

    dim3 blk(256);
    GP a{};

    // ---- batch: U = x@W1a, V = x@W1b, P = x@Wm_a ----
    a = GP{};
    a.M = NN; a.nch = 16; a.Kpad = 512;
    a.A0h = XFh; a.A0l = XFl; a.w0 = 512; a.ld0 = 512;
    a.jwh[0] = WTH;              a.jwl[0] = WTL;              a.jcf[0] = U; a.jb[0] = nullptr;
    a.jwh[1] = WTH + 256 * 512;  a.jwl[1] = WTL + 256 * 512;  a.jcf[1] = V; a.jb[1] = nullptr;
    a.jwh[2] = WTH + 256 * 1280; a.jwl[2] = WTL + 256 * 1280; a.jcf[2] = P; a.jb[2] = nullptr;
    a.njobs = 3;
    P0<<<dim3(79, 3), blk, SMEM_SZ>>>(a);

    // ---- EA = (relu(U[src]+V[dst]+ea@W1c+b1)) @ e_w2_0 + b2  [COMB, N-split] ----
    a = GP{};
    a.M = NE; a.nch = 8; a.Kpad = 256;
    a.I0 = SRC; a.I1 = DST; a.w0 = 256;
    a.Uf = U; a.Vf = V; a.EAT = eattr;
    a.W1c = e_w1_0 + (size_t)1024 * 256; a.B1 = e_b1_0;
    a.WtH = WTH + 256 * 1024; a.WtL = WTL + 256 * 1024;
    a.bias = e_b2_0; a.Ch = EAh; a.Cl = EAl;
    PC<<<dim3(1250, 2), blk, SMEM_HALF>>>(a);

    // ---- MSG = relu(EA@Wm_b + P[src] + bm) scattered (red.v2) into S[dst] ----
    a = GP{};
    a.M = NE; a.nch = 8; a.Kpad = 256;
    a.A0h = EAh; a.A0l = EAl; a.w0 = 256; a.ld0 = 256;
    a.WtH = WTH + 256 * 1792; a.WtL = WTL + 256 * 1792;
    a.bias = n_bm_0; a.G1 = P; a.IG1 = SRC; a.SDST = DST; a.Cf = S;
    P3<<<dim3(1250), blk, SMEM_SZ>>>(a);
    mean_kernel<<<NN, 256>>>();

    // ---- XH = relu([x, S] @ n_w1_0 + b) ----
    a = GP{};
    a.M = NN; a.nch = 24; a.Kpad = 768;
    a.A0h = XFh; a.A0l = XFl; a.w0 = 512; a.ld0 = 512;
    a.A1h = Shh; a.A1l = Sll; a.ld1 = 256;
    a.WtH = WTH + 256 * 2048; a.WtL = WTL + 256 * 2048;
    a.bias = n_b1_0; a.Ch = XHh; a.Cl = XHl;
    P1<<<dim3(79), blk, SMEM_SZ>>>(a);

    // ---- batch: U1 = XH@Wc_a + bc_a, V1 = XH@Wc_b + bc_b ----
    a = GP{};
    a.M = NN; a.nch = 8; a.Kpad = 256;
    a.A0h = XHh; a.A0l = XHl; a.w0 = 256; a.ld0 = 256;
    a.jwh[0] = WTH + 256 * 3584; a.jwl[0] = WTL + 256 * 3584; a.jcf[0] = U; a.jb[0] = BC;
    a.jwh[1] = WTH + 256 * 3840; a.jwl[1] = WTL + 256 * 3840; a.jcf[1] = V; a.jb[1] = BC + 256;
    a.njobs = 2;
    P0<<<dim3(79, 2), blk, SMEM_SZ>>>(a);

    // ---- EH2 = relu(EA@W11c + U1[src] + V1[dst] + e_b1_1) ----
    a = GP{};
    a.M = NE; a.nch = 8; a.Kpad = 256;
    a.A0h = EAh; a.A0l = EAl; a.w0 = 256; a.ld0 = 256;
    a.WtH = WTH + 256 * 2816; a.WtL = WTL + 256 * 2816;
    a.bias = e_b1_1; a.G1 = U; a.IG1 = SRC; a.G2 = V; a.IG2 = DST;
    a.Ch = EHh; a.Cl = EHl;
    P4<<<dim3(1250), blk, SMEM_SZ>>>(a);

    // ---- out = relu([EH2,EA] @ Wpred + bc_p) . p_w2 + b2  [PRED composed K=512] ----
    a = GP{};
    a.M = NE; a.nch = 16; a.Kpad = 512;
    a.A0h = EHh; a.A0l = EHl; a.w0 = 256; a.ld0 = 256;
    a.A1h = EAh; a.A1l = EAl; a.ld1 = 256;
    a.WtH = WTH + 256 * 3072; a.WtL = WTL + 256 * 3072;
    a.bias = BC + 512; a.PW2 = p_w2; a.OutP = out;
    P6<<<dim3(1250), blk, SMEM_SZ>>>(a);

    (void)in_sizes; (void)n_in; (void)out_size;
}

// round 15
// speedup vs baseline: 1.0500x; 1.0500x over previous
#include <cuda_runtime.h>
#include <cuda_bf16.h>
#include <cstdint>
#include <cstddef>

#define NE 160000
#define NN 10000
typedef unsigned short u16;
typedef unsigned int u32;

// ---------------- scratch (device globals) ----------------
__device__ u16 g_XFh[(size_t)NN * 512], g_XFl[(size_t)NN * 512];
__device__ u16 g_EAh[(size_t)NE * 256], g_EAl[(size_t)NE * 256];
__device__ u16 g_EHh[(size_t)NE * 256], g_EHl[(size_t)NE * 256];
__device__ u16 g_Shh[NN * 256], g_Sll[NN * 256];
__device__ u16 g_XHh[NN * 256], g_XHl[NN * 256];
__device__ float g_U[NN * 256], g_V[NN * 256], g_P[NN * 256];
__device__ float g_S[NN * 256];
__device__ float g_CNT[NN];
__device__ float g_BC[768];            // bc_a | bc_b | bc_p
__device__ int   g_SRC[NE], g_DST[NE];
__device__ int   g_IS64;
__device__ u16 g_WTH[256 * 4416], g_WTL[256 * 4416];

// ---------------- helpers ----------------
__device__ __forceinline__ u32 smem_u32(const void* p) {
    u32 a;
    asm("{ .reg .u64 t; cvta.to.shared.u64 t, %1; cvt.u32.u64 %0, t; }" : "=r"(a) : "l"(p));
    return a;
}
__device__ __forceinline__ void cp16(u32 dst, const void* src) {
    asm volatile("cp.async.ca.shared.global [%0], [%1], 16;" :: "r"(dst), "l"(src) : "memory");
}
__device__ __forceinline__ void ldsm4(u32* r, u32 addr) {
    asm volatile("ldmatrix.sync.aligned.m8n8.x4.shared.b16 {%0,%1,%2,%3}, [%4];"
                 : "=r"(r[0]), "=r"(r[1]), "=r"(r[2]), "=r"(r[3]) : "r"(addr));
}
__device__ __forceinline__ void mma_bf16(float* d, const u32* a, u32 b0, u32 b1) {
    asm volatile(
        "mma.sync.aligned.m16n8k16.row.col.f32.bf16.bf16.f32 "
        "{%0,%1,%2,%3}, {%4,%5,%6,%7}, {%8,%9}, {%0,%1,%2,%3};"
        : "+f"(d[0]), "+f"(d[1]), "+f"(d[2]), "+f"(d[3])
        : "r"(a[0]), "r"(a[1]), "r"(a[2]), "r"(a[3]), "r"(b0), "r"(b1));
}
__device__ __forceinline__ void sts128(u32 addr, u32 a, u32 b, u32 c, u32 d) {
    asm volatile("st.shared.v4.b32 [%0], {%1,%2,%3,%4};" :: "r"(addr), "r"(a), "r"(b), "r"(c), "r"(d) : "memory");
}
__device__ __forceinline__ void split2(float o0, float o1, u32& hp, u32& lp) {
    u32 b0 = __float_as_uint(o0), b1 = __float_as_uint(o1);
    hp = (b1 & 0xFFFF0000u) | (b0 >> 16);
    float l0 = o0 - __uint_as_float(b0 & 0xFFFF0000u);
    float l1 = o1 - __uint_as_float(b1 & 0xFFFF0000u);
    asm("cvt.rn.bf16x2.f32 %0, %1, %2;" : "=r"(lp) : "f"(l1), "f"(l0));
}
__device__ __forceinline__ void wt_store(size_t o, float v) {
    u32 b = __float_as_uint(v);
    g_WTH[o] = (u16)(b >> 16);
    __nv_bfloat16 lo = __float2bfloat16_rn(v - __uint_as_float(b & 0xFFFF0000u));
    g_WTL[o] = *(u16*)&lo;
}

#define RSB   80
#define STAGE 61440
#define EXTRA 11264
#define SMEM_SZ (2 * STAGE + EXTRA)

// ---------------- one consolidated setup kernel ----------------
struct WtEnt { const float* w; int K, off, stride, kofs; };
struct CompJob { const float* A; const float* B; int off, stride; };
struct SetupArgs {
    WtEnt we[8];
    CompJob ce[3];
    const float *n_b2_0, *W11a, *W11b, *e_b2_1, *p_w1, *p_b1;
    const int* ei32;
};

__global__ void setup_kernel(SetupArgs sa) {
    const int y = blockIdx.y;
    if (y < 8) {
        const WtEnt en = sa.we[y];
        int idx = blockIdx.x * blockDim.x + threadIdx.x;
        if (idx >= 256 * en.K) return;
        int n = idx / en.K, k = idx - n * en.K;
        wt_store((size_t)256 * en.off + (size_t)n * en.stride + en.kofs + k,
                 en.w[(size_t)k * 256 + n]);
    } else if (y < 11) {
        if (blockIdx.x >= 256) return;
        const CompJob en = sa.ce[y - 8];
        __shared__ float arow[256];
        int k = blockIdx.x, n = threadIdx.x;
        arow[n] = en.A[(size_t)k * 256 + n];
        __syncthreads();
        float s = 0.f;
        #pragma unroll 8
        for (int m = 0; m < 256; m++) s += arow[m] * en.B[(size_t)m * 256 + n];
        wt_store((size_t)256 * en.off + (size_t)n * en.stride + k, s);
    } else {
        if (blockIdx.x == 0) {
            int n = threadIdx.x;
            float va = 0.f, vb = 0.f, vp = 0.f;
            for (int m = 0; m < 256; m++) {
                float b2 = sa.n_b2_0[m], e2 = sa.e_b2_1[m];
                va += b2 * sa.W11a[(size_t)m * 256 + n];
                vb += b2 * sa.W11b[(size_t)m * 256 + n];
                vp += e2 * sa.p_w1[(size_t)m * 256 + n];
            }
            g_BC[n] = va;
            g_BC[256 + n] = vb;
            g_BC[512 + n] = vp + sa.p_b1[n];
        } else if (blockIdx.x == 1) {
            __shared__ int any_nonzero;
            if (threadIdx.x == 0) any_nonzero = 0;
            __syncthreads();
            for (int i = threadIdx.x; i < 2048; i += blockDim.x) {
                int pos = 2 * (i * (NE / 2048)) + 1;
                if (sa.ei32[pos] != 0) any_nonzero = 1;
            }
            __syncthreads();
            if (threadIdx.x == 0) g_IS64 = any_nonzero ? 0 : 1;
        } else {
            int idx = (blockIdx.x - 2) * blockDim.x + threadIdx.x;
            int stride = (gridDim.x - 2) * blockDim.x;
            for (int j = idx; j < NN * 256; j += stride) g_S[j] = 0.f;
            for (int j = idx; j < NN; j += stride) g_CNT[j] = 0.f;
        }
    }
}

// idx convert + count + out init + x split
__global__ void prep_kernel(const int* __restrict__ ei32, const float* __restrict__ x,
                            float* __restrict__ outp, const float* __restrict__ b2) {
    int i = blockIdx.x * blockDim.x + threadIdx.x;
    int stride = gridDim.x * blockDim.x;
    const int is64 = g_IS64;
    const float bv = b2[0];
    for (int j = i; j < NE; j += stride) {
        int s, d;
        if (is64) { s = ei32[2 * j]; d = ei32[2 * (NE + j)]; }
        else      { s = ei32[j];     d = ei32[NE + j]; }
        s = min(max(s, 0), NN - 1);
        d = min(max(d, 0), NN - 1);
        g_SRC[j] = s;
        g_DST[j] = d;
        atomicAdd(&g_CNT[d], 1.f);
        outp[j] = bv;
    }
    for (int j = i; j < NN * 512; j += stride) {
        float v = x[j];
        u32 b = __float_as_uint(v);
        g_XFh[j] = (u16)(b >> 16);
        __nv_bfloat16 lo = __float2bfloat16_rn(v - __uint_as_float(b & 0xFFFF0000u));
        g_XFl[j] = *(u16*)&lo;
    }
}

__global__ void mean_kernel() {
    int n = blockIdx.x, c = threadIdx.x;
    float v = g_S[n * 256 + c] / fmaxf(g_CNT[n], 1.f);
    u32 b = __float_as_uint(v);
    g_Shh[n * 256 + c] = (u16)(b >> 16);
    __nv_bfloat16 lo = __float2bfloat16_rn(v - __uint_as_float(b & 0xFFFF0000u));
    g_Sll[n * 256 + c] = *(u16*)&lo;
}

// ---------------- unified HMMA GEMM ----------------
struct GP {
    int M, nch, Kpad;
    const u16 *A0h, *A0l; const int* I0; int w0, ld0;
    const u16 *A1h, *A1l; const int* I1; int ld1;
    const u16 *WtH, *WtL;
    const float* bias;
    const float* G1; const int* IG1;
    const float* G2; const int* IG2;
    const int* SDST;
    float* Cf; u16 *Ch, *Cl;
    const float *Uf, *Vf, *EAT, *W1c, *B1;   // COMB
    const float* PW2; float* OutP;           // PRED
    const u16* jwh[3]; const u16* jwl[3]; float* jcf[3]; const float* jb[3]; int njobs;
};

template<bool RELU, bool SPLIT, bool ADD, bool SCAT, bool COMB, bool PRED>
__global__ void __launch_bounds__(256, 1) gemm3(GP p)
{
    extern __shared__ __align__(128) char smem[];
    const u32 sb = smem_u32(smem);
    const int tid = threadIdx.x;
    const int lane = tid & 31, wid = tid >> 5;
    const int warp_m = wid & 1, warp_n = wid >> 1;
    const int bm = blockIdx.x * 128;

    const u16* WtH = p.WtH; const u16* WtL = p.WtL; float* Cf = p.Cf;
    const float* bias = p.bias;
    if (p.njobs) {
        int jy = blockIdx.y;
        WtH = p.jwh[jy]; WtL = p.jwl[jy]; Cf = p.jcf[jy]; bias = p.jb[jy];
    }

    const int arow = tid >> 1, ahalf = tid & 1;
    const int gmc = min(bm + arow, p.M - 1);
    const int r0i = p.I0 ? p.I0[gmc] : gmc;
    const int r1i = p.I1 ? p.I1[gmc] : gmc;
    const u16* pa0h = p.A0h ? (p.A0h + (size_t)r0i * p.ld0) : nullptr;
    const u16* pa0l = p.A0l ? (p.A0l + (size_t)r0i * p.ld0) : nullptr;
    const u16* pa1h = p.A1h ? (p.A1h + (size_t)r1i * p.ld1) : nullptr;
    const u16* pa1l = p.A1l ? (p.A1l + (size_t)r1i * p.ld1) : nullptr;
    const u16* pbh = WtH + (size_t)tid * p.Kpad;
    const u16* pbl = WtL + (size_t)tid * p.Kpad;

    float acc[4][8][4];
    #pragma unroll
    for (int a = 0; a < 4; a++)
        #pragma unroll
        for (int b = 0; b < 8; b++)
            #pragma unroll
            for (int c = 0; c < 4; c++) acc[a][b][c] = 0.f;

    auto prefetchB = [&](int c) {
        const int k0 = c << 5;
        u32 db = sb + (c & 1) * STAGE + 20480 + (u32)tid * RSB;
        #pragma unroll
        for (int j = 0; j < 4; j++) {
            cp16(db + j * 16,         pbh + k0 + j * 8);
            cp16(db + 20480 + j * 16, pbl + k0 + j * 8);
        }
    };
    auto prefetchA = [&](int c) {
        const int k0 = c << 5;
        const u32 st = sb + (c & 1) * STAGE;
        const u16 *sh, *sl;
        int kk;
        if (k0 < p.w0) { sh = pa0h; sl = pa0l; kk = k0; }
        else           { sh = pa1h; sl = pa1l; kk = k0 - p.w0; }
        u32 da = st + (u32)arow * RSB + ahalf * 32;
        cp16(da,              sh + kk + ahalf * 16);
        cp16(da + 16,         sh + kk + ahalf * 16 + 8);
        cp16(da + 10240,      sl + kk + ahalf * 16);
        cp16(da + 10240 + 16, sl + kk + ahalf * 16 + 8);
    };

    // ---- COMB state ----
    float eav[6];
    float fu[16], fv[16];
    const float* w1ct = (const float*)(smem + 2 * STAGE);
    float* eas = (float*)(smem + 2 * STAGE + 8192);

    auto comb_load = [&](int c) {
        const int kb = (c << 5) + ahalf * 16;
        #pragma unroll
        for (int j = 0; j < 4; j++) {
            *(float4*)&fu[4 * j] = *(const float4*)&p.Uf[(size_t)r0i * 256 + kb + 4 * j];
            *(float4*)&fv[4 * j] = *(const float4*)&p.Vf[(size_t)r1i * 256 + kb + 4 * j];
        }
    };
    auto comb_convert = [&](int c) {
        const int kb = (c << 5) + ahalf * 16;
        const u32 st = sb + (c & 1) * STAGE;
        u32 hw[8], lw[8];
        #pragma unroll
        for (int j = 0; j < 8; j++) {
            float t[2];
            #pragma unroll
            for (int q = 0; q < 2; q++) {
                int kl = 2 * j + q;
                int k = kb + kl;
                float4 wa = *(const float4*)&w1ct[k * 8];
                float4 wb = *(const float4*)&w1ct[k * 8 + 4];
                float v = fu[kl] + fv[kl] + wb.z
                        + eav[0] * wa.x + eav[1] * wa.y + eav[2] * wa.z + eav[3] * wa.w
                        + eav[4] * wb.x + eav[5] * wb.y;
                t[q] = fmaxf(v, 0.f);
            }
            u32 b0 = __float_as_uint(t[0]), b1 = __float_as_uint(t[1]);
            hw[j] = (b1 & 0xFFFF0000u) | (b0 >> 16);
            float l0 = t[0] - __uint_as_float(b0 & 0xFFFF0000u);
            float l1 = t[1] - __uint_as_float(b1 & 0xFFFF0000u);
            asm("cvt.rn.bf16x2.f32 %0, %1, %2;" : "=r"(lw[j]) : "f"(l1), "f"(l0));
        }
        u32 da = st + (u32)arow * RSB + ahalf * 32;
        sts128(da,              hw[0], hw[1], hw[2], hw[3]);
        sts128(da + 16,         hw[4], hw[5], hw[6], hw[7]);
        sts128(da + 10240,      lw[0], lw[1], lw[2], lw[3]);
        sts128(da + 10240 + 16, lw[4], lw[5], lw[6], lw[7]);
    };

    // one k16 half of the MMA body
    auto do_mma = [&](int kk, u32 aH, u32 aL, u32 bH, u32 bL) {
        u32 Afh[4][4], Afl[4][4];
        #pragma unroll
        for (int mf = 0; mf < 4; mf++) {
            u32 off = (u32)(warp_m * 64 + mf * 16 + (lane & 15)) * RSB
                    + kk * 32 + ((lane >> 4) << 4);
            ldsm4(Afh[mf], aH + off);
            ldsm4(Afl[mf], aL + off);
        }
        #pragma unroll
        for (int nf = 0; nf < 4; nf++) {
            u32 off = (u32)(warp_n * 64 + nf * 16 + ((lane >> 4) & 1) * 8 + (lane & 7)) * RSB
                    + kk * 32 + ((lane >> 3) & 1) * 16;
            u32 bh[4], bl[4];
            ldsm4(bh, bH + off);
            ldsm4(bl, bL + off);
            #pragma unroll
            for (int mf = 0; mf < 4; mf++) {
                mma_bf16(acc[mf][2 * nf],     Afh[mf], bh[0], bh[1]);
                mma_bf16(acc[mf][2 * nf + 1], Afh[mf], bh[2], bh[3]);
            }
            #pragma unroll
            for (int mf = 0; mf < 4; mf++) {
                mma_bf16(acc[mf][2 * nf],     Afh[mf], bl[0], bl[1]);
                mma_bf16(acc[mf][2 * nf + 1], Afh[mf], bl[2], bl[3]);
            }
            #pragma unroll
            for (int mf = 0; mf < 4; mf++) {
                mma_bf16(acc[mf][2 * nf],     Afl[mf], bh[0], bh[1]);
                mma_bf16(acc[mf][2 * nf + 1], Afl[mf], bh[2], bh[3]);
            }
        }
    };

    // ---- prologue ----
    if constexpr (COMB) {
        float* w1w = (float*)(smem + 2 * STAGE);
        for (int i = tid; i < 2048; i += 256) {
            int k = i >> 3, jj = i & 7;
            float v = 0.f;
            if (jj < 6) v = p.W1c[jj * 256 + k];
            else if (jj == 6) v = p.B1[k];
            w1w[i] = v;
        }
        for (int i = tid; i < 768; i += 256) {
            int e = bm + i / 6, j = i % 6;
            eas[i] = (e < p.M) ? p.EAT[(size_t)e * 6 + j] : 0.f;
        }
        __syncthreads();
        #pragma unroll
        for (int j = 0; j < 6; j++) eav[j] = eas[arow * 6 + j];
        comb_load(0);
        prefetchB(0);
        asm volatile("cp.async.commit_group;" ::: "memory");
        comb_convert(0);
    } else {
        if constexpr (PRED) {
            ((float*)(smem + 2 * STAGE))[tid] = p.PW2[tid];
        }
        prefetchA(0); prefetchB(0);
        asm volatile("cp.async.commit_group;" ::: "memory");
    }

    // ---- mainloop ----
    for (int c = 0; c < p.nch; c++) {
        if (c + 1 < p.nch) {
            if constexpr (COMB) { prefetchB(c + 1); }
            else { prefetchA(c + 1); prefetchB(c + 1); }
            asm volatile("cp.async.commit_group;" ::: "memory");
            asm volatile("cp.async.wait_group 1;" ::: "memory");
        } else {
            asm volatile("cp.async.wait_group 0;" ::: "memory");
        }
        __syncthreads();

        const u32 st = sb + (c & 1) * STAGE;
        const u32 aH = st, aL = st + 10240, bH = st + 20480, bL = st + 40960;
        if constexpr (COMB) {
            // interleave: U/V loads live only across the second k16 half
            do_mma(0, aH, aL, bH, bL);
            if (c + 1 < p.nch) comb_load(c + 1);
            do_mma(1, aH, aL, bH, bL);
            if (c + 1 < p.nch) comb_convert(c + 1);
        } else {
            do_mma(0, aH, aL, bH, bL);
            do_mma(1, aH, aL, bH, bL);
        }
        __syncthreads();
    }

    // ---- epilogue ----
    const int gid = lane >> 2, tig = lane & 3;
    #pragma unroll
    for (int mf = 0; mf < 4; mf++) {
        #pragma unroll
        for (int half = 0; half < 2; half++) {
            const int r = bm + warp_m * 64 + mf * 16 + half * 8 + gid;
            if constexpr (PRED) {
                const float* w2s = (const float*)(smem + 2 * STAGE);
                float s = 0.f;
                if (r < p.M) {
                    #pragma unroll
                    for (int nidx = 0; nidx < 8; nidx++) {
                        const int col = warp_n * 64 + nidx * 8 + tig * 2;
                        float o0 = acc[mf][nidx][half * 2 + 0] + bias[col];
                        float o1 = acc[mf][nidx][half * 2 + 1] + bias[col + 1];
                        o0 = fmaxf(o0, 0.f); o1 = fmaxf(o1, 0.f);
                        s += o0 * w2s[col] + o1 * w2s[col + 1];
                    }
                }
                s += __shfl_xor_sync(0xffffffffu, s, 1);
                s += __shfl_xor_sync(0xffffffffu, s, 2);
                if (tig == 0 && r < p.M) atomicAdd(&p.OutP[r], s);
            } else if (r < p.M) {
                const float* ag1 = nullptr;
                const float* ag2 = nullptr;
                int sd = 0;
                if (ADD) {
                    ag1 = p.G1 + (size_t)(p.IG1 ? p.IG1[r] : r) * 256;
                    if (p.G2) ag2 = p.G2 + (size_t)(p.IG2 ? p.IG2[r] : r) * 256;
                }
                if (SCAT) sd = p.SDST[r];
                #pragma unroll
                for (int nidx = 0; nidx < 8; nidx++) {
                    const int col = warp_n * 64 + nidx * 8 + tig * 2;
                    float o0 = acc[mf][nidx][half * 2 + 0];
                    float o1 = acc[mf][nidx][half * 2 + 1];
                    if (bias) { o0 += bias[col]; o1 += bias[col + 1]; }
                    if (ADD) {
                        o0 += ag1[col]; o1 += ag1[col + 1];
                        if (ag2) { o0 += ag2[col]; o1 += ag2[col + 1]; }
                    }
                    if (RELU) { o0 = fmaxf(o0, 0.f); o1 = fmaxf(o1, 0.f); }
                    if (SCAT) {
                        asm volatile("red.global.add.v2.f32 [%0], {%1,%2};"
                                     :: "l"(&Cf[(size_t)sd * 256 + col]), "f"(o0), "f"(o1)
                                     : "memory");
                    } else if (SPLIT) {
                        u32 hp, lp;
                        split2(o0, o1, hp, lp);
                        *(u32*)&p.Ch[(size_t)r * 256 + col] = hp;
                        *(u32*)&p.Cl[(size_t)r * 256 + col] = lp;
                    } else {
                        *(float2*)&Cf[(size_t)r * 256 + col] = make_float2(o0, o1);
                    }
                }
            }
        }
    }
}

extern "C" void kernel_launch(void* const* d_in, const int* in_sizes, int n_in,
                              void* d_out, int out_size)
{
    const float* x      = (const float*)d_in[0];
    const int*   ei32   = (const int*)d_in[1];
    const float* eattr  = (const float*)d_in[2];
    const float* e_w1_0 = (const float*)d_in[3];
    const float* e_b1_0 = (const float*)d_in[4];
    const float* e_w2_0 = (const float*)d_in[5];
    const float* e_b2_0 = (const float*)d_in[6];
    const float* n_wm_0 = (const float*)d_in[7];
    const float* n_bm_0 = (const float*)d_in[8];
    const float* n_w1_0 = (const float*)d_in[9];
    const float* n_b1_0 = (const float*)d_in[10];
    const float* n_w2_0 = (const float*)d_in[11];
    const float* n_b2_0 = (const float*)d_in[12];
    const float* e_w1_1 = (const float*)d_in[13];
    const float* e_b1_1 = (const float*)d_in[14];
    const float* e_w2_1 = (const float*)d_in[15];
    const float* e_b2_1 = (const float*)d_in[16];
    // d_in[17..22]: layer-1 node model — dead code for the output
    const float* p_w1   = (const float*)d_in[23];
    const float* p_b1   = (const float*)d_in[24];
    const float* p_w2   = (const float*)d_in[25];
    const float* p_b2   = (const float*)d_in[26];
    float* out = (float*)d_out;

#define SYM(T, v, s) T* v; cudaGetSymbolAddress((void**)&v, s)
    SYM(u16, XFh, g_XFh); SYM(u16, XFl, g_XFl);
    SYM(u16, EAh, g_EAh); SYM(u16, EAl, g_EAl);
    SYM(u16, EHh, g_EHh); SYM(u16, EHl, g_EHl);
    SYM(u16, Shh, g_Shh); SYM(u16, Sll, g_Sll);
    SYM(u16, XHh, g_XHh); SYM(u16, XHl, g_XHl);
    SYM(float, U, g_U); SYM(float, V, g_V); SYM(float, P, g_P);
    SYM(float, S, g_S); SYM(float, BC, g_BC);
    SYM(int, SRC, g_SRC); SYM(int, DST, g_DST);
    SYM(u16, WTH, g_WTH); SYM(u16, WTL, g_WTL);
#undef SYM

#define P0 gemm3<false, false, false, false, false, false>
#define PC gemm3<false, true,  false, false, true,  false>
#define P3 gemm3<true,  false, true,  true,  false, false>
#define P1 gemm3<true,  true,  false, false, false, false>
#define P4 gemm3<true,  true,  true,  false, false, false>
#define P6 gemm3<true,  false, false, false, false, true >
    cudaFuncSetAttribute(P0, cudaFuncAttributeMaxDynamicSharedMemorySize, SMEM_SZ);
    cudaFuncSetAttribute(PC, cudaFuncAttributeMaxDynamicSharedMemorySize, SMEM_SZ);
    cudaFuncSetAttribute(P3, cudaFuncAttributeMaxDynamicSharedMemorySize, SMEM_SZ);
    cudaFuncSetAttribute(P1, cudaFuncAttributeMaxDynamicSharedMemorySize, SMEM_SZ);
    cudaFuncSetAttribute(P4, cudaFuncAttributeMaxDynamicSharedMemorySize, SMEM_SZ);
    cudaFuncSetAttribute(P6, cudaFuncAttributeMaxDynamicSharedMemorySize, SMEM_SZ);

    // weight map (k-units): W1a@0(512) W1b@512(512) e_w2_0@1024(256) Wm_a@1280(512)
    // Wm_b@1792(256) n_w1_0@2048(768) W11c@2816(256) [W21@p_w1 | p_w1]@3072(K=512)
    // Wc_a@3584(256) Wc_b@3840(256)
    SetupArgs sa{};
    sa.we[0] = { e_w1_0,             512, 0,    512, 0 };
    sa.we[1] = { e_w1_0 + 512 * 256, 512, 512,  512, 0 };
    sa.we[2] = { e_w2_0,             256, 1024, 256, 0 };
    sa.we[3] = { n_wm_0,             512, 1280, 512, 0 };
    sa.we[4] = { n_wm_0 + 512 * 256, 256, 1792, 256, 0 };
    sa.we[5] = { n_w1_0,             768, 2048, 768, 0 };
    sa.we[6] = { e_w1_1 + 512 * 256, 256, 2816, 256, 0 };
    sa.we[7] = { p_w1,               256, 3072, 512, 256 };
    sa.ce[0] = { n_w2_0, e_w1_1,             3584, 256 };
    sa.ce[1] = { n_w2_0, e_w1_1 + 256 * 256, 3840, 256 };
    sa.ce[2] = { e_w2_1, p_w1,               3072, 512 };
    sa.n_b2_0 = n_b2_0; sa.W11a = e_w1_1; sa.W11b = e_w1_1 + 256 * 256;
    sa.e_b2_1 = e_b2_1; sa.p_w1 = p_w1; sa.p_b1 = p_b1;
    sa.ei32 = ei32;
    setup_kernel<<<dim3(768, 12), 256>>>(sa);

    prep_kernel<<<2048, 256>>>(ei32, x, out, p_b2);

    dim3 blk(256);
    GP a{};

    // ---- batch: U = x@W1a, V = x@W1b, P = x@Wm_a ----
    a = GP{};
    a.M = NN; a.nch = 16; a.Kpad = 512;
    a.A0h = XFh; a.A0l = XFl; a.w0 = 512; a.ld0 = 512;
    a.jwh[0] = WTH;              a.jwl[0] = WTL;              a.jcf[0] = U; a.jb[0] = nullptr;
    a.jwh[1] = WTH + 256 * 512;  a.jwl[1] = WTL + 256 * 512;  a.jcf[1] = V; a.jb[1] = nullptr;
    a.jwh[2] = WTH + 256 * 1280; a.jwl[2] = WTL + 256 * 1280; a.jcf[2] = P; a.jb[2] = nullptr;
    a.njobs = 3;
    P0<<<dim3(79, 3), blk, SMEM_SZ>>>(a);

    // ---- EA = (relu(U[src]+V[dst]+ea@W1c+b1)) @ e_w2_0 + b2  [COMB] ----
    a = GP{};
    a.M = NE; a.nch = 8; a.Kpad = 256;
    a.I0 = SRC; a.I1 = DST; a.w0 = 256;
    a.Uf = U; a.Vf = V; a.EAT = eattr;
    a.W1c = e_w1_0 + (size_t)1024 * 256; a.B1 = e_b1_0;
    a.WtH = WTH + 256 * 1024; a.WtL = WTL + 256 * 1024;
    a.bias = e_b2_0; a.Ch = EAh; a.Cl = EAl;
    PC<<<dim3(1250), blk, SMEM_SZ>>>(a);

    // ---- MSG = relu(EA@Wm_b + P[src] + bm) scattered (red.v2) into S[dst] ----
    a = GP{};
    a.M = NE; a.nch = 8; a.Kpad = 256;
    a.A0h = EAh; a.A0l = EAl; a.w0 = 256; a.ld0 = 256;
    a.WtH = WTH + 256 * 1792; a.WtL = WTL + 256 * 1792;
    a.bias = n_bm_0; a.G1 = P; a.IG1 = SRC; a.SDST = DST; a.Cf = S;
    P3<<<dim3(1250), blk, SMEM_SZ>>>(a);
    mean_kernel<<<NN, 256>>>();

    // ---- XH = relu([x, S] @ n_w1_0 + b) ----
    a = GP{};
    a.M = NN; a.nch = 24; a.Kpad = 768;
    a.A0h = XFh; a.A0l = XFl; a.w0 = 512; a.ld0 = 512;
    a.A1h = Shh; a.A1l = Sll; a.ld1 = 256;
    a.WtH = WTH + 256 * 2048; a.WtL = WTL + 256 * 2048;
    a.bias = n_b1_0; a.Ch = XHh; a.Cl = XHl;
    P1<<<dim3(79), blk, SMEM_SZ>>>(a);

    // ---- batch: U1 = XH@Wc_a + bc_a, V1 = XH@Wc_b + bc_b ----
    a = GP{};
    a.M = NN; a.nch = 8; a.Kpad = 256;
    a.A0h = XHh; a.A0l = XHl; a.w0 = 256; a.ld0 = 256;
    a.jwh[0] = WTH + 256 * 3584; a.jwl[0] = WTL + 256 * 3584; a.jcf[0] = U; a.jb[0] = BC;
    a.jwh[1] = WTH + 256 * 3840; a.jwl[1] = WTL + 256 * 3840; a.jcf[1] = V; a.jb[1] = BC + 256;
    a.njobs = 2;
    P0<<<dim3(79, 2), blk, SMEM_SZ>>>(a);

    // ---- EH2 = relu(EA@W11c + U1[src] + V1[dst] + e_b1_1) ----
    a = GP{};
    a.M = NE; a.nch = 8; a.Kpad = 256;
    a.A0h = EAh; a.A0l = EAl; a.w0 = 256; a.ld0 = 256;
    a.WtH = WTH + 256 * 2816; a.WtL = WTL + 256 * 2816;
    a.bias = e_b1_1; a.G1 = U; a.IG1 = SRC; a.G2 = V; a.IG2 = DST;
    a.Ch = EHh; a.Cl = EHl;
    P4<<<dim3(1250), blk, SMEM_SZ>>>(a);

    // ---- out = relu([EH2,EA] @ Wpred + bc_p) . p_w2 + b2  [PRED composed K=512] ----
    a = GP{};
    a.M = NE; a.nch = 16; a.Kpad = 512;
    a.A0h = EHh; a.A0l = EHl; a.w0 = 256; a.ld0 = 256;
    a.A1h = EAh; a.A1l = EAl; a.ld1 = 256;
    a.WtH = WTH + 256 * 3072; a.WtL = WTL + 256 * 3072;
    a.bias = BC + 512; a.PW2 = p_w2; a.OutP = out;
    P6<<<dim3(1250), blk, SMEM_SZ>>>(a);

    (void)in_sizes; (void)n_in; (void)out_size;
}

// round 16
// speedup vs baseline: 1.0568x; 1.0065x over previous
#include <cuda_runtime.h>
#include <cuda_bf16.h>
#include <cstdint>
#include <cstddef>

#define NE 160000
#define NN 10000
typedef unsigned short u16;
typedef unsigned int u32;

// ---------------- scratch (device globals) ----------------
__device__ u16 g_XFh[(size_t)NN * 512], g_XFl[(size_t)NN * 512];
__device__ u16 g_EAh[(size_t)NE * 256], g_EAl[(size_t)NE * 256];
__device__ u16 g_EHh[(size_t)NE * 256], g_EHl[(size_t)NE * 256];
__device__ u16 g_Shh[NN * 256], g_Sll[NN * 256];
__device__ u16 g_XHh[NN * 256], g_XHl[NN * 256];
__device__ float g_U[NN * 256], g_V[NN * 256], g_P[NN * 256];
__device__ float g_S[NN * 256];
__device__ float g_CNT[NN];
__device__ float g_BC[768];            // bc_a | bc_b | bc_p
__device__ int   g_SRC[NE], g_DST[NE];
__device__ int   g_IS64;
__device__ u16 g_WTH[256 * 4416], g_WTL[256 * 4416];

// ---------------- helpers ----------------
__device__ __forceinline__ u32 smem_u32(const void* p) {
    u32 a;
    asm("{ .reg .u64 t; cvta.to.shared.u64 t, %1; cvt.u32.u64 %0, t; }" : "=r"(a) : "l"(p));
    return a;
}
__device__ __forceinline__ void cp16(u32 dst, const void* src) {
    asm volatile("cp.async.ca.shared.global [%0], [%1], 16;" :: "r"(dst), "l"(src) : "memory");
}
__device__ __forceinline__ void ldsm4(u32* r, u32 addr) {
    asm volatile("ldmatrix.sync.aligned.m8n8.x4.shared.b16 {%0,%1,%2,%3}, [%4];"
                 : "=r"(r[0]), "=r"(r[1]), "=r"(r[2]), "=r"(r[3]) : "r"(addr));
}
__device__ __forceinline__ void mma_bf16(float* d, const u32* a, u32 b0, u32 b1) {
    asm volatile(
        "mma.sync.aligned.m16n8k16.row.col.f32.bf16.bf16.f32 "
        "{%0,%1,%2,%3}, {%4,%5,%6,%7}, {%8,%9}, {%0,%1,%2,%3};"
        : "+f"(d[0]), "+f"(d[1]), "+f"(d[2]), "+f"(d[3])
        : "r"(a[0]), "r"(a[1]), "r"(a[2]), "r"(a[3]), "r"(b0), "r"(b1));
}
__device__ __forceinline__ void sts128(u32 addr, u32 a, u32 b, u32 c, u32 d) {
    asm volatile("st.shared.v4.b32 [%0], {%1,%2,%3,%4};" :: "r"(addr), "r"(a), "r"(b), "r"(c), "r"(d) : "memory");
}
__device__ __forceinline__ void split2(float o0, float o1, u32& hp, u32& lp) {
    u32 b0 = __float_as_uint(o0), b1 = __float_as_uint(o1);
    hp = (b1 & 0xFFFF0000u) | (b0 >> 16);
    float l0 = o0 - __uint_as_float(b0 & 0xFFFF0000u);
    float l1 = o1 - __uint_as_float(b1 & 0xFFFF0000u);
    asm("cvt.rn.bf16x2.f32 %0, %1, %2;" : "=r"(lp) : "f"(l1), "f"(l0));
}
__device__ __forceinline__ void wt_store(size_t o, float v) {
    u32 b = __float_as_uint(v);
    g_WTH[o] = (u16)(b >> 16);
    __nv_bfloat16 lo = __float2bfloat16_rn(v - __uint_as_float(b & 0xFFFF0000u));
    g_WTL[o] = *(u16*)&lo;
}

#define RSB   80
#define STAGE 61440
#define EXTRA 11264
#define SMEM_SZ (2 * STAGE + EXTRA)

// ---------------- one consolidated setup kernel ----------------
struct WtEnt { const float* w; int K, off, stride, kofs; };
struct CompJob { const float* A; const float* B; int off, stride; };
struct SetupArgs {
    WtEnt we[8];
    CompJob ce[3];
    const float *n_b2_0, *W11a, *W11b, *e_b2_1, *p_w1, *p_b1;
    const int* ei32;
};

__global__ void setup_kernel(SetupArgs sa) {
    const int y = blockIdx.y;
    if (y < 8) {
        const WtEnt en = sa.we[y];
        int idx = blockIdx.x * blockDim.x + threadIdx.x;
        if (idx >= 256 * en.K) return;
        int n = idx / en.K, k = idx - n * en.K;
        wt_store((size_t)256 * en.off + (size_t)n * en.stride + en.kofs + k,
                 en.w[(size_t)k * 256 + n]);
    } else if (y < 11) {
        if (blockIdx.x >= 256) return;
        const CompJob en = sa.ce[y - 8];
        __shared__ float arow[256];
        int k = blockIdx.x, n = threadIdx.x;
        arow[n] = en.A[(size_t)k * 256 + n];
        __syncthreads();
        float s = 0.f;
        #pragma unroll 8
        for (int m = 0; m < 256; m++) s += arow[m] * en.B[(size_t)m * 256 + n];
        wt_store((size_t)256 * en.off + (size_t)n * en.stride + k, s);
    } else {
        if (blockIdx.x == 0) {
            int n = threadIdx.x;
            float va = 0.f, vb = 0.f, vp = 0.f;
            for (int m = 0; m < 256; m++) {
                float b2 = sa.n_b2_0[m], e2 = sa.e_b2_1[m];
                va += b2 * sa.W11a[(size_t)m * 256 + n];
                vb += b2 * sa.W11b[(size_t)m * 256 + n];
                vp += e2 * sa.p_w1[(size_t)m * 256 + n];
            }
            g_BC[n] = va;
            g_BC[256 + n] = vb;
            g_BC[512 + n] = vp + sa.p_b1[n];
        } else if (blockIdx.x == 1) {
            __shared__ int any_nonzero;
            if (threadIdx.x == 0) any_nonzero = 0;
            __syncthreads();
            for (int i = threadIdx.x; i < 2048; i += blockDim.x) {
                int pos = 2 * (i * (NE / 2048)) + 1;
                if (sa.ei32[pos] != 0) any_nonzero = 1;
            }
            __syncthreads();
            if (threadIdx.x == 0) g_IS64 = any_nonzero ? 0 : 1;
        } else {
            int idx = (blockIdx.x - 2) * blockDim.x + threadIdx.x;
            int stride = (gridDim.x - 2) * blockDim.x;
            for (int j = idx; j < NN * 256; j += stride) g_S[j] = 0.f;
            for (int j = idx; j < NN; j += stride) g_CNT[j] = 0.f;
        }
    }
}

// idx convert + count + out init + x split
__global__ void prep_kernel(const int* __restrict__ ei32, const float* __restrict__ x,
                            float* __restrict__ outp, const float* __restrict__ b2) {
    int i = blockIdx.x * blockDim.x + threadIdx.x;
    int stride = gridDim.x * blockDim.x;
    const int is64 = g_IS64;
    const float bv = b2[0];
    for (int j = i; j < NE; j += stride) {
        int s, d;
        if (is64) { s = ei32[2 * j]; d = ei32[2 * (NE + j)]; }
        else      { s = ei32[j];     d = ei32[NE + j]; }
        s = min(max(s, 0), NN - 1);
        d = min(max(d, 0), NN - 1);
        g_SRC[j] = s;
        g_DST[j] = d;
        atomicAdd(&g_CNT[d], 1.f);
        outp[j] = bv;
    }
    for (int j = i; j < NN * 512; j += stride) {
        float v = x[j];
        u32 b = __float_as_uint(v);
        g_XFh[j] = (u16)(b >> 16);
        __nv_bfloat16 lo = __float2bfloat16_rn(v - __uint_as_float(b & 0xFFFF0000u));
        g_XFl[j] = *(u16*)&lo;
    }
}

__global__ void mean_kernel() {
    int n = blockIdx.x, c = threadIdx.x;
    float v = g_S[n * 256 + c] / fmaxf(g_CNT[n], 1.f);
    u32 b = __float_as_uint(v);
    g_Shh[n * 256 + c] = (u16)(b >> 16);
    __nv_bfloat16 lo = __float2bfloat16_rn(v - __uint_as_float(b & 0xFFFF0000u));
    g_Sll[n * 256 + c] = *(u16*)&lo;
}

// ---------------- unified HMMA GEMM ----------------
struct GP {
    int M, nch, Kpad;
    const u16 *A0h, *A0l; const int* I0; int w0, ld0;
    const u16 *A1h, *A1l; const int* I1; int ld1;
    const u16 *WtH, *WtL;
    const float* bias;
    const float* G1; const int* IG1;
    const float* G2; const int* IG2;
    const int* SDST;
    float* Cf; u16 *Ch, *Cl;
    const float *Uf, *Vf, *EAT, *W1c, *B1;   // COMB
    const float* PW2; float* OutP;           // PRED
    const u16* jwh[3]; const u16* jwl[3]; float* jcf[3]; const float* jb[3]; int njobs;
};

template<bool RELU, bool SPLIT, bool ADD, bool SCAT, bool COMB, bool PRED>
__global__ void __launch_bounds__(256, 1) gemm3(GP p)
{
    extern __shared__ __align__(128) char smem[];
    const u32 sb = smem_u32(smem);
    const int tid = threadIdx.x;
    const int lane = tid & 31, wid = tid >> 5;
    const int warp_m = wid & 1, warp_n = wid >> 1;
    const int bm = blockIdx.x * 128;

    const u16* WtH = p.WtH; const u16* WtL = p.WtL; float* Cf = p.Cf;
    const float* bias = p.bias;
    if (p.njobs) {
        int jy = blockIdx.y;
        WtH = p.jwh[jy]; WtL = p.jwl[jy]; Cf = p.jcf[jy]; bias = p.jb[jy];
    }

    const int arow = tid >> 1, ahalf = tid & 1;
    const int gmc = min(bm + arow, p.M - 1);
    const int r0i = p.I0 ? p.I0[gmc] : gmc;
    const int r1i = p.I1 ? p.I1[gmc] : gmc;
    const u16* pa0h = p.A0h ? (p.A0h + (size_t)r0i * p.ld0) : nullptr;
    const u16* pa0l = p.A0l ? (p.A0l + (size_t)r0i * p.ld0) : nullptr;
    const u16* pa1h = p.A1h ? (p.A1h + (size_t)r1i * p.ld1) : nullptr;
    const u16* pa1l = p.A1l ? (p.A1l + (size_t)r1i * p.ld1) : nullptr;
    const u16* pbh = WtH + (size_t)tid * p.Kpad;
    const u16* pbl = WtL + (size_t)tid * p.Kpad;

    float acc[4][8][4];
    #pragma unroll
    for (int a = 0; a < 4; a++)
        #pragma unroll
        for (int b = 0; b < 8; b++)
            #pragma unroll
            for (int c = 0; c < 4; c++) acc[a][b][c] = 0.f;

    auto prefetchB = [&](int c) {
        const int k0 = c << 5;
        u32 db = sb + (c & 1) * STAGE + 20480 + (u32)tid * RSB;
        #pragma unroll
        for (int j = 0; j < 4; j++) {
            cp16(db + j * 16,         pbh + k0 + j * 8);
            cp16(db + 20480 + j * 16, pbl + k0 + j * 8);
        }
    };
    auto prefetchA = [&](int c) {
        const int k0 = c << 5;
        const u32 st = sb + (c & 1) * STAGE;
        const u16 *sh, *sl;
        int kk;
        if (k0 < p.w0) { sh = pa0h; sl = pa0l; kk = k0; }
        else           { sh = pa1h; sl = pa1l; kk = k0 - p.w0; }
        u32 da = st + (u32)arow * RSB + ahalf * 32;
        cp16(da,              sh + kk + ahalf * 16);
        cp16(da + 16,         sh + kk + ahalf * 16 + 8);
        cp16(da + 10240,      sl + kk + ahalf * 16);
        cp16(da + 10240 + 16, sl + kk + ahalf * 16 + 8);
    };

    // ---- COMB state ----
    float eav[6];
    float fu[16], fv[16];
    const float* w1ct = (const float*)(smem + 2 * STAGE);
    float* eas = (float*)(smem + 2 * STAGE + 8192);

    auto comb_load = [&](int c) {
        const int kb = (c << 5) + ahalf * 16;
        #pragma unroll
        for (int j = 0; j < 4; j++) {
            *(float4*)&fu[4 * j] = *(const float4*)&p.Uf[(size_t)r0i * 256 + kb + 4 * j];
            *(float4*)&fv[4 * j] = *(const float4*)&p.Vf[(size_t)r1i * 256 + kb + 4 * j];
        }
    };
    auto comb_convert = [&](int c) {
        const int kb = (c << 5) + ahalf * 16;
        const u32 st = sb + (c & 1) * STAGE;
        u32 hw[8], lw[8];
        #pragma unroll
        for (int j = 0; j < 8; j++) {
            float t[2];
            #pragma unroll
            for (int q = 0; q < 2; q++) {
                int kl = 2 * j + q;
                int k = kb + kl;
                float4 wa = *(const float4*)&w1ct[k * 8];
                float4 wb = *(const float4*)&w1ct[k * 8 + 4];
                float v = fu[kl] + fv[kl] + wb.z
                        + eav[0] * wa.x + eav[1] * wa.y + eav[2] * wa.z + eav[3] * wa.w
                        + eav[4] * wb.x + eav[5] * wb.y;
                t[q] = fmaxf(v, 0.f);
            }
            u32 b0 = __float_as_uint(t[0]), b1 = __float_as_uint(t[1]);
            hw[j] = (b1 & 0xFFFF0000u) | (b0 >> 16);
            float l0 = t[0] - __uint_as_float(b0 & 0xFFFF0000u);
            float l1 = t[1] - __uint_as_float(b1 & 0xFFFF0000u);
            asm("cvt.rn.bf16x2.f32 %0, %1, %2;" : "=r"(lw[j]) : "f"(l1), "f"(l0));
        }
        u32 da = st + (u32)arow * RSB + ahalf * 32;
        sts128(da,              hw[0], hw[1], hw[2], hw[3]);
        sts128(da + 16,         hw[4], hw[5], hw[6], hw[7]);
        sts128(da + 10240,      lw[0], lw[1], lw[2], lw[3]);
        sts128(da + 10240 + 16, lw[4], lw[5], lw[6], lw[7]);
    };

    // one k16 half of the MMA body
    auto do_mma = [&](int kk, u32 aH, u32 aL, u32 bH, u32 bL) {
        u32 Afh[4][4], Afl[4][4];
        #pragma unroll
        for (int mf = 0; mf < 4; mf++) {
            u32 off = (u32)(warp_m * 64 + mf * 16 + (lane & 15)) * RSB
                    + kk * 32 + ((lane >> 4) << 4);
            ldsm4(Afh[mf], aH + off);
            ldsm4(Afl[mf], aL + off);
        }
        #pragma unroll
        for (int nf = 0; nf < 4; nf++) {
            u32 off = (u32)(warp_n * 64 + nf * 16 + ((lane >> 4) & 1) * 8 + (lane & 7)) * RSB
                    + kk * 32 + ((lane >> 3) & 1) * 16;
            u32 bh[4], bl[4];
            ldsm4(bh, bH + off);
            ldsm4(bl, bL + off);
            #pragma unroll
            for (int mf = 0; mf < 4; mf++) {
                mma_bf16(acc[mf][2 * nf],     Afh[mf], bh[0], bh[1]);
                mma_bf16(acc[mf][2 * nf + 1], Afh[mf], bh[2], bh[3]);
            }
            #pragma unroll
            for (int mf = 0; mf < 4; mf++) {
                mma_bf16(acc[mf][2 * nf],     Afh[mf], bl[0], bl[1]);
                mma_bf16(acc[mf][2 * nf + 1], Afh[mf], bl[2], bl[3]);
            }
            #pragma unroll
            for (int mf = 0; mf < 4; mf++) {
                mma_bf16(acc[mf][2 * nf],     Afl[mf], bh[0], bh[1]);
                mma_bf16(acc[mf][2 * nf + 1], Afl[mf], bh[2], bh[3]);
            }
        }
    };

    // ---- prologue ----
    if constexpr (COMB) {
        float* w1w = (float*)(smem + 2 * STAGE);
        for (int i = tid; i < 2048; i += 256) {
            int k = i >> 3, jj = i & 7;
            float v = 0.f;
            if (jj < 6) v = p.W1c[jj * 256 + k];
            else if (jj == 6) v = p.B1[k];
            w1w[i] = v;
        }
        for (int i = tid; i < 768; i += 256) {
            int e = bm + i / 6, j = i % 6;
            eas[i] = (e < p.M) ? p.EAT[(size_t)e * 6 + j] : 0.f;
        }
        __syncthreads();
        #pragma unroll
        for (int j = 0; j < 6; j++) eav[j] = eas[arow * 6 + j];
        comb_load(0);
        prefetchB(0);
        asm volatile("cp.async.commit_group;" ::: "memory");
        comb_convert(0);
    } else {
        if constexpr (PRED) {
            ((float*)(smem + 2 * STAGE))[tid] = p.PW2[tid];
        }
        prefetchA(0); prefetchB(0);
        asm volatile("cp.async.commit_group;" ::: "memory");
    }

    // ---- mainloop: single barrier per chunk ----
    // order: wait_group 0 (chunk c landed) -> barrier (all warps done with
    // MMA(c-1), so buffer (c+1)&1 is free and chunk-c data is published) ->
    // issue prefetch(c+1) -> MMA(c).
    for (int c = 0; c < p.nch; c++) {
        asm volatile("cp.async.wait_group 0;" ::: "memory");
        __syncthreads();
        if (c + 1 < p.nch) {
            if constexpr (COMB) { prefetchB(c + 1); }
            else { prefetchA(c + 1); prefetchB(c + 1); }
            asm volatile("cp.async.commit_group;" ::: "memory");
        }

        const u32 st = sb + (c & 1) * STAGE;
        const u32 aH = st, aL = st + 10240, bH = st + 20480, bL = st + 40960;
        if constexpr (COMB) {
            do_mma(0, aH, aL, bH, bL);
            if (c + 1 < p.nch) comb_load(c + 1);
            do_mma(1, aH, aL, bH, bL);
            if (c + 1 < p.nch) comb_convert(c + 1);
        } else {
            do_mma(0, aH, aL, bH, bL);
            do_mma(1, aH, aL, bH, bL);
        }
    }

    // ---- epilogue ----
    const int gid = lane >> 2, tig = lane & 3;
    #pragma unroll
    for (int mf = 0; mf < 4; mf++) {
        #pragma unroll
        for (int half = 0; half < 2; half++) {
            const int r = bm + warp_m * 64 + mf * 16 + half * 8 + gid;
            if constexpr (PRED) {
                const float* w2s = (const float*)(smem + 2 * STAGE);
                float s = 0.f;
                if (r < p.M) {
                    #pragma unroll
                    for (int nidx = 0; nidx < 8; nidx++) {
                        const int col = warp_n * 64 + nidx * 8 + tig * 2;
                        float o0 = acc[mf][nidx][half * 2 + 0] + bias[col];
                        float o1 = acc[mf][nidx][half * 2 + 1] + bias[col + 1];
                        o0 = fmaxf(o0, 0.f); o1 = fmaxf(o1, 0.f);
                        s += o0 * w2s[col] + o1 * w2s[col + 1];
                    }
                }
                s += __shfl_xor_sync(0xffffffffu, s, 1);
                s += __shfl_xor_sync(0xffffffffu, s, 2);
                if (tig == 0 && r < p.M) atomicAdd(&p.OutP[r], s);
            } else if (r < p.M) {
                const float* ag1 = nullptr;
                const float* ag2 = nullptr;
                int sd = 0;
                if (ADD) {
                    ag1 = p.G1 + (size_t)(p.IG1 ? p.IG1[r] : r) * 256;
                    if (p.G2) ag2 = p.G2 + (size_t)(p.IG2 ? p.IG2[r] : r) * 256;
                }
                if (SCAT) sd = p.SDST[r];
                #pragma unroll
                for (int nidx = 0; nidx < 8; nidx++) {
                    const int col = warp_n * 64 + nidx * 8 + tig * 2;
                    float o0 = acc[mf][nidx][half * 2 + 0];
                    float o1 = acc[mf][nidx][half * 2 + 1];
                    if (bias) { o0 += bias[col]; o1 += bias[col + 1]; }
                    if (ADD) {
                        o0 += ag1[col]; o1 += ag1[col + 1];
                        if (ag2) { o0 += ag2[col]; o1 += ag2[col + 1]; }
                    }
                    if (RELU) { o0 = fmaxf(o0, 0.f); o1 = fmaxf(o1, 0.f); }
                    if (SCAT) {
                        asm volatile("red.global.add.v2.f32 [%0], {%1,%2};"
                                     :: "l"(&Cf[(size_t)sd * 256 + col]), "f"(o0), "f"(o1)
                                     : "memory");
                    } else if (SPLIT) {
                        u32 hp, lp;
                        split2(o0, o1, hp, lp);
                        *(u32*)&p.Ch[(size_t)r * 256 + col] = hp;
                        *(u32*)&p.Cl[(size_t)r * 256 + col] = lp;
                    } else {
                        *(float2*)&Cf[(size_t)r * 256 + col] = make_float2(o0, o1);
                    }
                }
            }
        }
    }
}

extern "C" void kernel_launch(void* const* d_in, const int* in_sizes, int n_in,
                              void* d_out, int out_size)
{
    const float* x      = (const float*)d_in[0];
    const int*   ei32   = (const int*)d_in[1];
    const float* eattr  = (const float*)d_in[2];
    const float* e_w1_0 = (const float*)d_in[3];
    const float* e_b1_0 = (const float*)d_in[4];
    const float* e_w2_0 = (const float*)d_in[5];
    const float* e_b2_0 = (const float*)d_in[6];
    const float* n_wm_0 = (const float*)d_in[7];
    const float* n_bm_0 = (const float*)d_in[8];
    const float* n_w1_0 = (const float*)d_in[9];
    const float* n_b1_0 = (const float*)d_in[10];
    const float* n_w2_0 = (const float*)d_in[11];
    const float* n_b2_0 = (const float*)d_in[12];
    const float* e_w1_1 = (const float*)d_in[13];
    const float* e_b1_1 = (const float*)d_in[14];
    const float* e_w2_1 = (const float*)d_in[15];
    const float* e_b2_1 = (const float*)d_in[16];
    // d_in[17..22]: layer-1 node model — dead code for the output
    const float* p_w1   = (const float*)d_in[23];
    const float* p_b1   = (const float*)d_in[24];
    const float* p_w2   = (const float*)d_in[25];
    const float* p_b2   = (const float*)d_in[26];
    float* out = (float*)d_out;

#define SYM(T, v, s) T* v; cudaGetSymbolAddress((void**)&v, s)
    SYM(u16, XFh, g_XFh); SYM(u16, XFl, g_XFl);
    SYM(u16, EAh, g_EAh); SYM(u16, EAl, g_EAl);
    SYM(u16, EHh, g_EHh); SYM(u16, EHl, g_EHl);
    SYM(u16, Shh, g_Shh); SYM(u16, Sll, g_Sll);
    SYM(u16, XHh, g_XHh); SYM(u16, XHl, g_XHl);
    SYM(float, U, g_U); SYM(float, V, g_V); SYM(float, P, g_P);
    SYM(float, S, g_S); SYM(float, BC, g_BC);
    SYM(int, SRC, g_SRC); SYM(int, DST, g_DST);
    SYM(u16, WTH, g_WTH); SYM(u16, WTL, g_WTL);
#undef SYM

#define P0 gemm3<false, false, false, false, false, false>
#define PC gemm3<false, true,  false, false, true,  false>
#define P3 gemm3<true,  false, true,  true,  false, false>
#define P1 gemm3<true,  true,  false, false, false, false>
#define P4 gemm3<true,  true,  true,  false, false, false>
#define P6 gemm3<true,  false, false, false, false, true >
    cudaFuncSetAttribute(P0, cudaFuncAttributeMaxDynamicSharedMemorySize, SMEM_SZ);
    cudaFuncSetAttribute(PC, cudaFuncAttributeMaxDynamicSharedMemorySize, SMEM_SZ);
    cudaFuncSetAttribute(P3, cudaFuncAttributeMaxDynamicSharedMemorySize, SMEM_SZ);
    cudaFuncSetAttribute(P1, cudaFuncAttributeMaxDynamicSharedMemorySize, SMEM_SZ);
    cudaFuncSetAttribute(P4, cudaFuncAttributeMaxDynamicSharedMemorySize, SMEM_SZ);
    cudaFuncSetAttribute(P6, cudaFuncAttributeMaxDynamicSharedMemorySize, SMEM_SZ);

    // weight map (k-units): W1a@0(512) W1b@512(512) e_w2_0@1024(256) Wm_a@1280(512)
    // Wm_b@1792(256) n_w1_0@2048(768) W11c@2816(256) [W21@p_w1 | p_w1]@3072(K=512)
    // Wc_a@3584(256) Wc_b@3840(256)
    SetupArgs sa{};
    sa.we[0] = { e_w1_0,             512, 0,    512, 0 };
    sa.we[1] = { e_w1_0 + 512 * 256, 512, 512,  512, 0 };
    sa.we[2] = { e_w2_0,             256, 1024, 256, 0 };
    sa.we[3] = { n_wm_0,             512, 1280, 512, 0 };
    sa.we[4] = { n_wm_0 + 512 * 256, 256, 1792, 256, 0 };
    sa.we[5] = { n_w1_0,             768, 2048, 768, 0 };
    sa.we[6] = { e_w1_1 + 512 * 256, 256, 2816, 256, 0 };
    sa.we[7] = { p_w1,               256, 3072, 512, 256 };
    sa.ce[0] = { n_w2_0, e_w1_1,             3584, 256 };
    sa.ce[1] = { n_w2_0, e_w1_1 + 256 * 256, 3840, 256 };
    sa.ce[2] = { e_w2_1, p_w1,               3072, 512 };
    sa.n_b2_0 = n_b2_0; sa.W11a = e_w1_1; sa.W11b = e_w1_1 + 256 * 256;
    sa.e_b2_1 = e_b2_1; sa.p_w1 = p_w1; sa.p_b1 = p_b1;
    sa.ei32 = ei32;
    setup_kernel<<<dim3(768, 12), 256>>>(sa);

    prep_kernel<<<2048, 256>>>(ei32, x, out, p_b2);

    dim3 blk(256);
    GP a{};

    // ---- batch: U = x@W1a, V = x@W1b, P = x@Wm_a ----
    a = GP{};
    a.M = NN; a.nch = 16; a.Kpad = 512;
    a.A0h = XFh; a.A0l = XFl; a.w0 = 512; a.ld0 = 512;
    a.jwh[0] = WTH;              a.jwl[0] = WTL;              a.jcf[0] = U; a.jb[0] = nullptr;
    a.jwh[1] = WTH + 256 * 512;  a.jwl[1] = WTL + 256 * 512;  a.jcf[1] = V; a.jb[1] = nullptr;
    a.jwh[2] = WTH + 256 * 1280; a.jwl[2] = WTL + 256 * 1280; a.jcf[2] = P; a.jb[2] = nullptr;
    a.njobs = 3;
    P0<<<dim3(79, 3), blk, SMEM_SZ>>>(a);

    // ---- EA = (relu(U[src]+V[dst]+ea@W1c+b1)) @ e_w2_0 + b2  [COMB] ----
    a = GP{};
    a.M = NE; a.nch = 8; a.Kpad = 256;
    a.I0 = SRC; a.I1 = DST; a.w0 = 256;
    a.Uf = U; a.Vf = V; a.EAT = eattr;
    a.W1c = e_w1_0 + (size_t)1024 * 256; a.B1 = e_b1_0;
    a.WtH = WTH + 256 * 1024; a.WtL = WTL + 256 * 1024;
    a.bias = e_b2_0; a.Ch = EAh; a.Cl = EAl;
    PC<<<dim3(1250), blk, SMEM_SZ>>>(a);

    // ---- MSG = relu(EA@Wm_b + P[src] + bm) scattered (red.v2) into S[dst] ----
    a = GP{};
    a.M = NE; a.nch = 8; a.Kpad = 256;
    a.A0h = EAh; a.A0l = EAl; a.w0 = 256; a.ld0 = 256;
    a.WtH = WTH + 256 * 1792; a.WtL = WTL + 256 * 1792;
    a.bias = n_bm_0; a.G1 = P; a.IG1 = SRC; a.SDST = DST; a.Cf = S;
    P3<<<dim3(1250), blk, SMEM_SZ>>>(a);
    mean_kernel<<<NN, 256>>>();

    // ---- XH = relu([x, S] @ n_w1_0 + b) ----
    a = GP{};
    a.M = NN; a.nch = 24; a.Kpad = 768;
    a.A0h = XFh; a.A0l = XFl; a.w0 = 512; a.ld0 = 512;
    a.A1h = Shh; a.A1l = Sll; a.ld1 = 256;
    a.WtH = WTH + 256 * 2048; a.WtL = WTL + 256 * 2048;
    a.bias = n_b1_0; a.Ch = XHh; a.Cl = XHl;
    P1<<<dim3(79), blk, SMEM_SZ>>>(a);

    // ---- batch: U1 = XH@Wc_a + bc_a, V1 = XH@Wc_b + bc_b ----
    a = GP{};
    a.M = NN; a.nch = 8; a.Kpad = 256;
    a.A0h = XHh; a.A0l = XHl; a.w0 = 256; a.ld0 = 256;
    a.jwh[0] = WTH + 256 * 3584; a.jwl[0] = WTL + 256 * 3584; a.jcf[0] = U; a.jb[0] = BC;
    a.jwh[1] = WTH + 256 * 3840; a.jwl[1] = WTL + 256 * 3840; a.jcf[1] = V; a.jb[1] = BC + 256;
    a.njobs = 2;
    P0<<<dim3(79, 2), blk, SMEM_SZ>>>(a);

    // ---- EH2 = relu(EA@W11c + U1[src] + V1[dst] + e_b1_1) ----
    a = GP{};
    a.M = NE; a.nch = 8; a.Kpad = 256;
    a.A0h = EAh; a.A0l = EAl; a.w0 = 256; a.ld0 = 256;
    a.WtH = WTH + 256 * 2816; a.WtL = WTL + 256 * 2816;
    a.bias = e_b1_1; a.G1 = U; a.IG1 = SRC; a.G2 = V; a.IG2 = DST;
    a.Ch = EHh; a.Cl = EHl;
    P4<<<dim3(1250), blk, SMEM_SZ>>>(a);

    // ---- out = relu([EH2,EA] @ Wpred + bc_p) . p_w2 + b2  [PRED composed K=512] ----
    a = GP{};
    a.M = NE; a.nch = 16; a.Kpad = 512;
    a.A0h = EHh; a.A0l = EHl; a.w0 = 256; a.ld0 = 256;
    a.A1h = EAh; a.A1l = EAl; a.ld1 = 256;
    a.WtH = WTH + 256 * 3072; a.WtL = WTL + 256 * 3072;
    a.bias = BC + 512; a.PW2 = p_w2; a.OutP = out;
    P6<<<dim3(1250), blk, SMEM_SZ>>>(a);

    (void)in_sizes; (void)n_in; (void)out_size;
}